// round 11
// baseline (speedup 1.0000x reference)
#include <cuda_runtime.h>
#include <cuda_fp16.h>
#include <cstdint>

#define N_NODES  100000
#define N_EDGES  3200000
#define N_GRAPHS 256
#define IN_DIM   128
#define HID_DIM  128
#define OUT_DIM  64

// ---------------- scratch (static device globals; no allocation) ----------------
__device__ __half g_xh  [(size_t)N_NODES * IN_DIM];   // 25.6 MB  x in fp16
__device__ __half g_agg1[(size_t)N_NODES * IN_DIM];   // 25.6 MB  layer-1 mean (fp16)
__device__ __half g_h   [(size_t)N_NODES * HID_DIM];  // 25.6 MB  hidden (fp16)
__device__ __half g_Wcat[HID_DIM * 256];              // [out][k] k = concat(Wl1, Wr1)
__device__ int   g_count [N_NODES];
__device__ int   g_rowptr[N_NODES + 1];
__device__ int   g_wcur  [N_NODES];
__device__ int   g_col   [N_EDGES];                   // CSR col = src, grouped by dst
__device__ int   g_bsum[128];
__device__ float g_poolL[N_GRAPHS * HID_DIM];
__device__ float g_poolR[N_GRAPHS * HID_DIM];
__device__ float g_cnt [N_GRAPHS];
__device__ int   g_is64;

__device__ __forceinline__ void mma16816(float* c, const uint32_t* a, uint32_t b0, uint32_t b1) {
    asm volatile(
        "mma.sync.aligned.m16n8k16.row.col.f32.f16.f16.f32 "
        "{%0,%1,%2,%3}, {%4,%5,%6,%7}, {%8,%9}, {%0,%1,%2,%3};"
        : "+f"(c[0]), "+f"(c[1]), "+f"(c[2]), "+f"(c[3])
        : "r"(a[0]), "r"(a[1]), "r"(a[2]), "r"(a[3]), "r"(b0), "r"(b1));
}

// ---------------- kernels ----------------

// setup: zero counters/pools, build fp16 Wcat, convert x -> fp16, detect dtype (block 0).
__global__ void k_setup(const int* __restrict__ ei32,
                        const float* __restrict__ Wl, const float* __restrict__ Wr,
                        const float4* __restrict__ x4) {
    int i = blockIdx.x * blockDim.x + threadIdx.x;
    int stride = gridDim.x * blockDim.x;
    for (int j = i; j < N_NODES; j += stride) g_count[j] = 0;
    for (int j = i; j < N_GRAPHS * HID_DIM; j += stride) { g_poolL[j] = 0.f; g_poolR[j] = 0.f; }
    if (i < N_GRAPHS) g_cnt[i] = 0.f;
    for (int j = i; j < HID_DIM * 256; j += stride) {
        int o = j >> 8, k = j & 255;
        float v = (k < 128) ? Wl[o * 128 + k] : Wr[o * 128 + (k - 128)];
        g_Wcat[o * 256 + k] = __float2half_rn(v);
    }
    // x fp32 -> fp16
    {
        uint2* dst = (uint2*)g_xh;
        const int total = N_NODES * IN_DIM / 4;
        for (int j = i; j < total; j += stride) {
            float4 v = __ldg(&x4[j]);
            __half2 h0 = __floats2half2_rn(v.x, v.y);
            __half2 h1 = __floats2half2_rn(v.z, v.w);
            uint2 u;
            u.x = *(unsigned*)&h0;
            u.y = *(unsigned*)&h1;
            dst[j] = u;
        }
    }
    if (blockIdx.x == 0) {
        __shared__ int any_nonzero;
        if (threadIdx.x == 0) any_nonzero = 0;
        __syncthreads();
        for (int j = threadIdx.x; j < 2048; j += blockDim.x) {
            long long pos = 2LL * ((long long)j * 1553LL + 1) + 1;  // odd words
            if (pos < 2LL * N_EDGES) {
                if (ei32[pos] != 0) atomicOr(&any_nonzero, 1);
            }
        }
        __syncthreads();
        if (threadIdx.x == 0) g_is64 = any_nonzero ? 0 : 1;
    }
}

// CSR build: histogram of dst (2 edges per thread, vector loads)
__global__ void k_hist(const void* __restrict__ ei) {
    const int is64 = g_is64;
    int i = blockIdx.x * blockDim.x + threadIdx.x;
    int stride = gridDim.x * blockDim.x;
    const int E2 = N_EDGES / 2;
    if (is64) {
        const longlong2* d2 = (const longlong2*)((const long long*)ei + N_EDGES);
        for (int e = i; e < E2; e += stride) {
            longlong2 v = __ldg(&d2[e]);
            int d0 = min(max((int)v.x, 0), N_NODES - 1);
            int d1 = min(max((int)v.y, 0), N_NODES - 1);
            atomicAdd(&g_count[d0], 1);
            atomicAdd(&g_count[d1], 1);
        }
    } else {
        const int2* d2 = (const int2*)((const int*)ei + N_EDGES);
        for (int e = i; e < E2; e += stride) {
            int2 v = __ldg(&d2[e]);
            int d0 = min(max(v.x, 0), N_NODES - 1);
            int d1 = min(max(v.y, 0), N_NODES - 1);
            atomicAdd(&g_count[d0], 1);
            atomicAdd(&g_count[d1], 1);
        }
    }
}

// scan phase 1: per-block (1024-elem) exclusive scan, coalesced
__global__ void k_scan1() {
    __shared__ int sh[1024];
    int t = threadIdx.x;
    int n = blockIdx.x * 1024 + t;
    int v = (n < N_NODES) ? g_count[n] : 0;
    sh[t] = v;
    __syncthreads();
    for (int off = 1; off < 1024; off <<= 1) {
        int u = (t >= off) ? sh[t - off] : 0;
        __syncthreads();
        sh[t] += u;
        __syncthreads();
    }
    if (n < N_NODES) g_rowptr[n] = sh[t] - v;   // exclusive within block
    if (t == 1023) g_bsum[blockIdx.x] = sh[1023];
}

// scan phase 2+3 merged: every block redundantly scans the 98 block sums in
// smem (trivial), then applies offsets and inits write cursors.
__global__ void k_scan3() {
    __shared__ int sincl[128];   // inclusive scan of block sums
    __shared__ int sorig[128];
    const int NB = (N_NODES + 1023) / 1024;   // 98
    int t = threadIdx.x;   // 256 threads
    if (t < 128) {
        int v = (t < NB) ? g_bsum[t] : 0;
        sincl[t] = v;
        sorig[t] = v;
    }
    __syncthreads();
    for (int off = 1; off < 128; off <<= 1) {
        int u = 0;
        if (t < 128 && t >= off) u = sincl[t - off];
        __syncthreads();
        if (t < 128) sincl[t] += u;
        __syncthreads();
    }
    int i = blockIdx.x * blockDim.x + t;
    if (i < N_NODES) {
        int blk = i >> 10;
        int excl = sincl[blk] - sorig[blk];
        int r = g_rowptr[i] + excl;
        g_rowptr[i] = r;
        g_wcur[i] = r;
    }
    if (i == 0) g_rowptr[N_NODES] = N_EDGES;
}

// CSR build: place src ids grouped by dst (2 edges per thread, vector loads)
__global__ void k_fill(const void* __restrict__ ei) {
    const int is64 = g_is64;
    int i = blockIdx.x * blockDim.x + threadIdx.x;
    int stride = gridDim.x * blockDim.x;
    const int E2 = N_EDGES / 2;
    if (is64) {
        const longlong2* s2 = (const longlong2*)ei;
        const longlong2* d2 = (const longlong2*)((const long long*)ei + N_EDGES);
        for (int e = i; e < E2; e += stride) {
            longlong2 sv = __ldg(&s2[e]);
            longlong2 dv = __ldg(&d2[e]);
            int s0 = min(max((int)sv.x, 0), N_NODES - 1);
            int s1 = min(max((int)sv.y, 0), N_NODES - 1);
            int d0 = min(max((int)dv.x, 0), N_NODES - 1);
            int d1 = min(max((int)dv.y, 0), N_NODES - 1);
            g_col[atomicAdd(&g_wcur[d0], 1)] = s0;
            g_col[atomicAdd(&g_wcur[d1], 1)] = s1;
        }
    } else {
        const int2* s2 = (const int2*)ei;
        const int2* d2 = (const int2*)((const int*)ei + N_EDGES);
        for (int e = i; e < E2; e += stride) {
            int2 sv = __ldg(&s2[e]);
            int2 dv = __ldg(&d2[e]);
            int s0 = min(max(sv.x, 0), N_NODES - 1);
            int s1 = min(max(sv.y, 0), N_NODES - 1);
            int d0 = min(max(dv.x, 0), N_NODES - 1);
            int d1 = min(max(dv.y, 0), N_NODES - 1);
            g_col[atomicAdd(&g_wcur[d0], 1)] = s0;
            g_col[atomicAdd(&g_wcur[d1], 1)] = s1;
        }
    }
}

// layer-1 aggregation (warp per node), 2 edges per warp-iter via uint4.
// Inner loop accumulates in fp16 (HADD2); folds to fp32 once per 32-edge
// chunk (fp16 chain <= 16 adds per lane-half -> negligible rounding).
__global__ void k_agg1() {
    int lane = threadIdx.x & 31;
    int n = (blockIdx.x * blockDim.x + threadIdx.x) >> 5;
    if (n >= N_NODES) return;
    int beg = g_rowptr[n], end = g_rowptr[n + 1];
    int half = lane >> 4, l16 = lane & 15;
    float acc[8] = {0.f, 0.f, 0.f, 0.f, 0.f, 0.f, 0.f, 0.f};
    const uint4* x4 = (const uint4*)g_xh;     // row = 16 uint4 (8 halves each)
    const __half2 hz = __float2half2_rn(0.f);
    for (int e0 = beg; e0 < end; e0 += 32) {
        int myc = (e0 + lane < end) ? g_col[e0 + lane] : -1;
        int m = min(32, end - e0);
        int npair = (m + 1) >> 1;
        __half2 ha0 = hz, ha1 = hz, ha2 = hz, ha3 = hz;
        #pragma unroll 4
        for (int j = 0; j < npair; j++) {
            int s0 = __shfl_sync(0xffffffff, myc, 2 * j);
            int s1 = __shfl_sync(0xffffffff, myc, 2 * j + 1);
            int s = half ? s1 : s0;
            if (s >= 0) {
                uint4 v = __ldg(&x4[(size_t)s * 16 + l16]);
                ha0 = __hadd2(ha0, *(__half2*)&v.x);
                ha1 = __hadd2(ha1, *(__half2*)&v.y);
                ha2 = __hadd2(ha2, *(__half2*)&v.z);
                ha3 = __hadd2(ha3, *(__half2*)&v.w);
            }
        }
        float2 f0 = __half22float2(ha0);
        float2 f1 = __half22float2(ha1);
        float2 f2 = __half22float2(ha2);
        float2 f3 = __half22float2(ha3);
        acc[0] += f0.x; acc[1] += f0.y; acc[2] += f1.x; acc[3] += f1.y;
        acc[4] += f2.x; acc[5] += f2.y; acc[6] += f3.x; acc[7] += f3.y;
    }
#pragma unroll
    for (int c = 0; c < 8; c++) acc[c] += __shfl_xor_sync(0xffffffff, acc[c], 16);
    if (half == 0) {
        float r = 1.0f / fmaxf((float)(end - beg), 1.0f);
        __half2 p0 = __floats2half2_rn(acc[0] * r, acc[1] * r);
        __half2 p1 = __floats2half2_rn(acc[2] * r, acc[3] * r);
        __half2 p2 = __floats2half2_rn(acc[4] * r, acc[5] * r);
        __half2 p3 = __floats2half2_rn(acc[6] * r, acc[7] * r);
        uint4 u;
        u.x = *(unsigned*)&p0; u.y = *(unsigned*)&p1;
        u.z = *(unsigned*)&p2; u.w = *(unsigned*)&p3;
        ((uint4*)g_agg1)[(size_t)n * 16 + l16] = u;
    }
}

// layer-1 GEMM on tensor cores:
//   h = relu( concat(agg1, x) @ Wcat^T + b1 ),  fp16 operands, fp32 accum.
__global__ void __launch_bounds__(256) k_gemm1_mma(const float* __restrict__ b1) {
    __shared__ __half sA[128][72];   // 64 data halves + 8 pad
    __shared__ __half sW[128][72];
    __shared__ float  sb[128];

    int tid = threadIdx.x;
    int lane = tid & 31;
    int w = tid >> 5;
    int n0 = blockIdx.x * 128;

    if (tid < 128) sb[tid] = __ldg(&b1[tid]);

    float acc[16][4];
#pragma unroll
    for (int t = 0; t < 16; t++)
#pragma unroll
        for (int j = 0; j < 4; j++) acc[t][j] = 0.f;

    const uint4* A1 = (const uint4*)g_agg1;
    const uint4* AX = (const uint4*)g_xh;
    const uint4* WC = (const uint4*)g_Wcat;

    for (int c = 0; c < 4; c++) {
        for (int i = tid; i < 1024; i += 256) {
            int r = i >> 3, c8 = i & 7;
            int node = min(n0 + r, N_NODES - 1);
            uint4 va = (c < 2) ? __ldg(&A1[(size_t)node * 16 + c * 8 + c8])
                               : __ldg(&AX[(size_t)node * 16 + (c - 2) * 8 + c8]);
            *(uint4*)&sA[r][c8 * 8] = va;
            uint4 vw = __ldg(&WC[r * 32 + c * 8 + c8]);
            *(uint4*)&sW[r][c8 * 8] = vw;
        }
        __syncthreads();

#pragma unroll
        for (int ks = 0; ks < 4; ks++) {
            uint32_t a[4];
            int ar = w * 16 + (lane >> 2);
            int ah = ks * 16 + (lane & 3) * 2;
            a[0] = *(const uint32_t*)&sA[ar][ah];
            a[1] = *(const uint32_t*)&sA[ar + 8][ah];
            a[2] = *(const uint32_t*)&sA[ar][ah + 8];
            a[3] = *(const uint32_t*)&sA[ar + 8][ah + 8];
#pragma unroll
            for (int t = 0; t < 16; t++) {
                int br = t * 8 + (lane >> 2);
                uint32_t b0 = *(const uint32_t*)&sW[br][ah];
                uint32_t b1r = *(const uint32_t*)&sW[br][ah + 8];
                mma16816(acc[t], a, b0, b1r);
            }
        }
        __syncthreads();
    }

    int row = w * 16 + (lane >> 2);
    int node0 = n0 + row;
    int node1 = node0 + 8;
#pragma unroll
    for (int t = 0; t < 16; t++) {
        int col = t * 8 + (lane & 3) * 2;
        float b0f = sb[col], b1f = sb[col + 1];
        if (node0 < N_NODES) {
            __half2 p = __floats2half2_rn(fmaxf(acc[t][0] + b0f, 0.f),
                                          fmaxf(acc[t][1] + b1f, 0.f));
            *(uint32_t*)&g_h[(size_t)node0 * 128 + col] = *(uint32_t*)&p;
        }
        if (node1 < N_NODES) {
            __half2 p = __floats2half2_rn(fmaxf(acc[t][2] + b0f, 0.f),
                                          fmaxf(acc[t][3] + b1f, 0.f));
            *(uint32_t*)&g_h[(size_t)node1 * 128 + col] = *(uint32_t*)&p;
        }
    }
}

// layer-2 aggregation fused with pooling (warp per node), fp16 inner accumulate
__global__ void k_agg2pool(const void* __restrict__ batch) {
    const int is64 = g_is64;
    int lane = threadIdx.x & 31;
    int n = (blockIdx.x * blockDim.x + threadIdx.x) >> 5;
    if (n >= N_NODES) return;
    int beg = g_rowptr[n], end = g_rowptr[n + 1];
    int half = lane >> 4, l16 = lane & 15;
    float acc[8] = {0.f, 0.f, 0.f, 0.f, 0.f, 0.f, 0.f, 0.f};
    const uint4* h4 = (const uint4*)g_h;
    const __half2 hz = __float2half2_rn(0.f);
    for (int e0 = beg; e0 < end; e0 += 32) {
        int myc = (e0 + lane < end) ? g_col[e0 + lane] : -1;
        int m = min(32, end - e0);
        int npair = (m + 1) >> 1;
        __half2 ha0 = hz, ha1 = hz, ha2 = hz, ha3 = hz;
        #pragma unroll 4
        for (int j = 0; j < npair; j++) {
            int s0 = __shfl_sync(0xffffffff, myc, 2 * j);
            int s1 = __shfl_sync(0xffffffff, myc, 2 * j + 1);
            int s = half ? s1 : s0;
            if (s >= 0) {
                uint4 v = __ldg(&h4[(size_t)s * 16 + l16]);
                ha0 = __hadd2(ha0, *(__half2*)&v.x);
                ha1 = __hadd2(ha1, *(__half2*)&v.y);
                ha2 = __hadd2(ha2, *(__half2*)&v.z);
                ha3 = __hadd2(ha3, *(__half2*)&v.w);
            }
        }
        float2 f0 = __half22float2(ha0);
        float2 f1 = __half22float2(ha1);
        float2 f2 = __half22float2(ha2);
        float2 f3 = __half22float2(ha3);
        acc[0] += f0.x; acc[1] += f0.y; acc[2] += f1.x; acc[3] += f1.y;
        acc[4] += f2.x; acc[5] += f2.y; acc[6] += f3.x; acc[7] += f3.y;
    }
#pragma unroll
    for (int c = 0; c < 8; c++) acc[c] += __shfl_xor_sync(0xffffffff, acc[c], 16);

    int g;
    if (is64) g = (int)((const long long*)batch)[n];
    else      g = ((const int*)batch)[n];
    g = min(max(g, 0), N_GRAPHS - 1);

    if (half == 0) {
        float r = 1.0f / fmaxf((float)(end - beg), 1.0f);
        float* pL = g_poolL + g * 128 + l16 * 8;
        asm volatile("red.global.add.v4.f32 [%0], {%1,%2,%3,%4};"
                     :: "l"(pL), "f"(acc[0] * r), "f"(acc[1] * r), "f"(acc[2] * r), "f"(acc[3] * r) : "memory");
        asm volatile("red.global.add.v4.f32 [%0], {%1,%2,%3,%4};"
                     :: "l"(pL + 4), "f"(acc[4] * r), "f"(acc[5] * r), "f"(acc[6] * r), "f"(acc[7] * r) : "memory");

        uint4 hv = __ldg(&h4[(size_t)n * 16 + l16]);
        float2 f0 = __half22float2(*(__half2*)&hv.x);
        float2 f1 = __half22float2(*(__half2*)&hv.y);
        float2 f2 = __half22float2(*(__half2*)&hv.z);
        float2 f3 = __half22float2(*(__half2*)&hv.w);
        float* pR = g_poolR + g * 128 + l16 * 8;
        asm volatile("red.global.add.v4.f32 [%0], {%1,%2,%3,%4};"
                     :: "l"(pR), "f"(f0.x), "f"(f0.y), "f"(f1.x), "f"(f1.y) : "memory");
        asm volatile("red.global.add.v4.f32 [%0], {%1,%2,%3,%4};"
                     :: "l"(pR + 4), "f"(f2.x), "f"(f2.y), "f"(f3.x), "f"(f3.y) : "memory");
        if (lane == 0) atomicAdd(&g_cnt[g], 1.0f);
    }
}

// final: out[g][o] = ( poolL[g]@Wl2[o]^T + poolR[g]@Wr2[o]^T ) / max(cnt,1) + b2[o]
__global__ void k_final(const float* __restrict__ Wl2, const float* __restrict__ Wr2,
                        const float* __restrict__ b2, float* __restrict__ out) {
    __shared__ float pl[128];
    __shared__ float pr[128];
    int g = blockIdx.x;
    int t = threadIdx.x;   // 64 threads
    pl[t]      = g_poolL[g * 128 + t];
    pl[t + 64] = g_poolL[g * 128 + t + 64];
    pr[t]      = g_poolR[g * 128 + t];
    pr[t + 64] = g_poolR[g * 128 + t + 64];
    __syncthreads();
    float c = fmaxf(g_cnt[g], 1.0f);
    float acc = 0.f;
    const float4* wl4 = (const float4*)&Wl2[t * 128];
    const float4* wr4 = (const float4*)&Wr2[t * 128];
#pragma unroll 8
    for (int k4 = 0; k4 < 32; k4++) {
        float4 wl = __ldg(&wl4[k4]);
        float4 wr = __ldg(&wr4[k4]);
        int k = 4 * k4;
        acc += pl[k]     * wl.x + pl[k + 1] * wl.y + pl[k + 2] * wl.z + pl[k + 3] * wl.w;
        acc += pr[k]     * wr.x + pr[k + 1] * wr.y + pr[k + 2] * wr.z + pr[k + 3] * wr.w;
    }
    out[g * 64 + t] = acc / c + __ldg(&b2[t]);
}

// ---------------- launch ----------------
extern "C" void kernel_launch(void* const* d_in, const int* in_sizes, int n_in,
                              void* d_out, int out_size) {
    const float* x     = (const float*)d_in[0];
    const void*  ei    = d_in[1];
    const void*  batch = d_in[2];
    const float* Wl1   = (const float*)d_in[3];
    const float* Wr1   = (const float*)d_in[4];
    const float* b1    = (const float*)d_in[5];
    const float* Wl2   = (const float*)d_in[6];
    const float* Wr2   = (const float*)d_in[7];
    const float* b2    = (const float*)d_in[8];
    float* out = (float*)d_out;

    // setup (zero + Wcat + x->fp16 + dtype detect)
    k_setup<<<2048, 256>>>((const int*)ei, Wl1, Wr1, (const float4*)x);

    // build CSR grouped by dst
    k_hist<<<2048, 256>>>(ei);
    k_scan1<<<(N_NODES + 1023) / 1024, 1024>>>();
    k_scan3<<<(N_NODES + 255) / 256, 256>>>();
    k_fill<<<2048, 256>>>(ei);

    // layer 1: gather-mean then tensor-core gemm+relu
    k_agg1<<<(N_NODES * 32 + 255) / 256, 256>>>();
    k_gemm1_mma<<<(N_NODES + 127) / 128, 256>>>(b1);

    // layer 2 aggregation fused with pooling
    k_agg2pool<<<(N_NODES * 32 + 255) / 256, 256>>>(batch);

    // tiny final GEMMs [256,128]x[128,64]
    k_final<<<N_GRAPHS, 64>>>(Wl2, Wr2, b2, out);
}

// round 12
// speedup vs baseline: 1.0264x; 1.0264x over previous
#include <cuda_runtime.h>
#include <cuda_fp16.h>
#include <cstdint>

#define N_NODES  100000
#define N_EDGES  3200000
#define N_GRAPHS 256
#define IN_DIM   128
#define HID_DIM  128
#define OUT_DIM  64

// ---------------- scratch (static device globals; no allocation) ----------------
__device__ __half g_xh  [(size_t)N_NODES * IN_DIM];   // 25.6 MB  x in fp16
__device__ __half g_agg1[(size_t)N_NODES * IN_DIM];   // 25.6 MB  layer-1 mean (fp16)
__device__ __half g_h   [(size_t)N_NODES * HID_DIM];  // 25.6 MB  hidden (fp16)
__device__ __half g_Wcat[HID_DIM * 256];              // [out][k] k = concat(Wl1, Wr1)
__device__ int   g_count [N_NODES];
__device__ int   g_rowptr[N_NODES + 1];
__device__ int   g_wcur  [N_NODES];
__device__ int   g_col   [N_EDGES];                   // CSR col = src, grouped by dst
__device__ int   g_bsum[128];
__device__ float g_poolL[N_GRAPHS * HID_DIM];
__device__ float g_poolR[N_GRAPHS * HID_DIM];
__device__ float g_cnt [N_GRAPHS];
__device__ int   g_is64;

__device__ __forceinline__ void mma16816(float* c, const uint32_t* a, uint32_t b0, uint32_t b1) {
    asm volatile(
        "mma.sync.aligned.m16n8k16.row.col.f32.f16.f16.f32 "
        "{%0,%1,%2,%3}, {%4,%5,%6,%7}, {%8,%9}, {%0,%1,%2,%3};"
        : "+f"(c[0]), "+f"(c[1]), "+f"(c[2]), "+f"(c[3])
        : "r"(a[0]), "r"(a[1]), "r"(a[2]), "r"(a[3]), "r"(b0), "r"(b1));
}

// ---------------- kernels ----------------

// pre (critical path): zero hist counters + detect index dtype (block 0).
__global__ void k_pre(const int* __restrict__ ei32) {
    int i = blockIdx.x * blockDim.x + threadIdx.x;
    int stride = gridDim.x * blockDim.x;
    for (int j = i; j < N_NODES; j += stride) g_count[j] = 0;
    if (blockIdx.x == 0) {
        __shared__ int any_nonzero;
        if (threadIdx.x == 0) any_nonzero = 0;
        __syncthreads();
        for (int j = threadIdx.x; j < 2048; j += blockDim.x) {
            long long pos = 2LL * ((long long)j * 1553LL + 1) + 1;  // odd words
            if (pos < 2LL * N_EDGES) {
                if (ei32[pos] != 0) atomicOr(&any_nonzero, 1);
            }
        }
        __syncthreads();
        if (threadIdx.x == 0) g_is64 = any_nonzero ? 0 : 1;
    }
}

// side-stream setup: build fp16 Wcat, convert x -> fp16, zero pools.
__global__ void k_setupB(const float* __restrict__ Wl, const float* __restrict__ Wr,
                         const float4* __restrict__ x4) {
    int i = blockIdx.x * blockDim.x + threadIdx.x;
    int stride = gridDim.x * blockDim.x;
    for (int j = i; j < N_GRAPHS * HID_DIM; j += stride) { g_poolL[j] = 0.f; g_poolR[j] = 0.f; }
    if (i < N_GRAPHS) g_cnt[i] = 0.f;
    for (int j = i; j < HID_DIM * 256; j += stride) {
        int o = j >> 8, k = j & 255;
        float v = (k < 128) ? Wl[o * 128 + k] : Wr[o * 128 + (k - 128)];
        g_Wcat[o * 256 + k] = __float2half_rn(v);
    }
    uint2* dst = (uint2*)g_xh;
    const int total = N_NODES * IN_DIM / 4;
    for (int j = i; j < total; j += stride) {
        float4 v = __ldg(&x4[j]);
        __half2 h0 = __floats2half2_rn(v.x, v.y);
        __half2 h1 = __floats2half2_rn(v.z, v.w);
        uint2 u;
        u.x = *(unsigned*)&h0;
        u.y = *(unsigned*)&h1;
        dst[j] = u;
    }
}

// CSR build: histogram of dst (2 edges per thread, vector loads)
__global__ void k_hist(const void* __restrict__ ei) {
    const int is64 = g_is64;
    int i = blockIdx.x * blockDim.x + threadIdx.x;
    int stride = gridDim.x * blockDim.x;
    const int E2 = N_EDGES / 2;
    if (is64) {
        const longlong2* d2 = (const longlong2*)((const long long*)ei + N_EDGES);
        for (int e = i; e < E2; e += stride) {
            longlong2 v = __ldg(&d2[e]);
            int d0 = min(max((int)v.x, 0), N_NODES - 1);
            int d1 = min(max((int)v.y, 0), N_NODES - 1);
            atomicAdd(&g_count[d0], 1);
            atomicAdd(&g_count[d1], 1);
        }
    } else {
        const int2* d2 = (const int2*)((const int*)ei + N_EDGES);
        for (int e = i; e < E2; e += stride) {
            int2 v = __ldg(&d2[e]);
            int d0 = min(max(v.x, 0), N_NODES - 1);
            int d1 = min(max(v.y, 0), N_NODES - 1);
            atomicAdd(&g_count[d0], 1);
            atomicAdd(&g_count[d1], 1);
        }
    }
}

// scan phase 1: per-block (1024-elem) exclusive scan, coalesced
__global__ void k_scan1() {
    __shared__ int sh[1024];
    int t = threadIdx.x;
    int n = blockIdx.x * 1024 + t;
    int v = (n < N_NODES) ? g_count[n] : 0;
    sh[t] = v;
    __syncthreads();
    for (int off = 1; off < 1024; off <<= 1) {
        int u = (t >= off) ? sh[t - off] : 0;
        __syncthreads();
        sh[t] += u;
        __syncthreads();
    }
    if (n < N_NODES) g_rowptr[n] = sh[t] - v;   // exclusive within block
    if (t == 1023) g_bsum[blockIdx.x] = sh[1023];
}

// scan phase 2+3 merged: every block redundantly scans the 98 block sums in
// smem (trivial), then applies offsets and inits write cursors.
__global__ void k_scan3() {
    __shared__ int sincl[128];   // inclusive scan of block sums
    __shared__ int sorig[128];
    const int NB = (N_NODES + 1023) / 1024;   // 98
    int t = threadIdx.x;   // 256 threads
    if (t < 128) {
        int v = (t < NB) ? g_bsum[t] : 0;
        sincl[t] = v;
        sorig[t] = v;
    }
    __syncthreads();
    for (int off = 1; off < 128; off <<= 1) {
        int u = 0;
        if (t < 128 && t >= off) u = sincl[t - off];
        __syncthreads();
        if (t < 128) sincl[t] += u;
        __syncthreads();
    }
    int i = blockIdx.x * blockDim.x + t;
    if (i < N_NODES) {
        int blk = i >> 10;
        int excl = sincl[blk] - sorig[blk];
        int r = g_rowptr[i] + excl;
        g_rowptr[i] = r;
        g_wcur[i] = r;
    }
    if (i == 0) g_rowptr[N_NODES] = N_EDGES;
}

// CSR build: place src ids grouped by dst (2 edges per thread, vector loads)
__global__ void k_fill(const void* __restrict__ ei) {
    const int is64 = g_is64;
    int i = blockIdx.x * blockDim.x + threadIdx.x;
    int stride = gridDim.x * blockDim.x;
    const int E2 = N_EDGES / 2;
    if (is64) {
        const longlong2* s2 = (const longlong2*)ei;
        const longlong2* d2 = (const longlong2*)((const long long*)ei + N_EDGES);
        for (int e = i; e < E2; e += stride) {
            longlong2 sv = __ldg(&s2[e]);
            longlong2 dv = __ldg(&d2[e]);
            int s0 = min(max((int)sv.x, 0), N_NODES - 1);
            int s1 = min(max((int)sv.y, 0), N_NODES - 1);
            int d0 = min(max((int)dv.x, 0), N_NODES - 1);
            int d1 = min(max((int)dv.y, 0), N_NODES - 1);
            g_col[atomicAdd(&g_wcur[d0], 1)] = s0;
            g_col[atomicAdd(&g_wcur[d1], 1)] = s1;
        }
    } else {
        const int2* s2 = (const int2*)ei;
        const int2* d2 = (const int2*)((const int*)ei + N_EDGES);
        for (int e = i; e < E2; e += stride) {
            int2 sv = __ldg(&s2[e]);
            int2 dv = __ldg(&d2[e]);
            int s0 = min(max(sv.x, 0), N_NODES - 1);
            int s1 = min(max(sv.y, 0), N_NODES - 1);
            int d0 = min(max(dv.x, 0), N_NODES - 1);
            int d1 = min(max(dv.y, 0), N_NODES - 1);
            g_col[atomicAdd(&g_wcur[d0], 1)] = s0;
            g_col[atomicAdd(&g_wcur[d1], 1)] = s1;
        }
    }
}

// layer-1 aggregation (warp per node), 2 edges per warp-iter via uint4, fp32 accum.
__global__ void k_agg1() {
    int lane = threadIdx.x & 31;
    int n = (blockIdx.x * blockDim.x + threadIdx.x) >> 5;
    if (n >= N_NODES) return;
    int beg = g_rowptr[n], end = g_rowptr[n + 1];
    int half = lane >> 4, l16 = lane & 15;
    float acc[8] = {0.f, 0.f, 0.f, 0.f, 0.f, 0.f, 0.f, 0.f};
    const uint4* x4 = (const uint4*)g_xh;     // row = 16 uint4 (8 halves each)
    for (int e0 = beg; e0 < end; e0 += 32) {
        int myc = (e0 + lane < end) ? g_col[e0 + lane] : -1;
        int m = min(32, end - e0);
        int npair = (m + 1) >> 1;
        #pragma unroll 4
        for (int j = 0; j < npair; j++) {
            int s0 = __shfl_sync(0xffffffff, myc, 2 * j);
            int s1 = __shfl_sync(0xffffffff, myc, 2 * j + 1);
            int s = half ? s1 : s0;
            if (s >= 0) {
                uint4 v = __ldg(&x4[(size_t)s * 16 + l16]);
                float2 f0 = __half22float2(*(__half2*)&v.x);
                float2 f1 = __half22float2(*(__half2*)&v.y);
                float2 f2 = __half22float2(*(__half2*)&v.z);
                float2 f3 = __half22float2(*(__half2*)&v.w);
                acc[0] += f0.x; acc[1] += f0.y; acc[2] += f1.x; acc[3] += f1.y;
                acc[4] += f2.x; acc[5] += f2.y; acc[6] += f3.x; acc[7] += f3.y;
            }
        }
    }
#pragma unroll
    for (int c = 0; c < 8; c++) acc[c] += __shfl_xor_sync(0xffffffff, acc[c], 16);
    if (half == 0) {
        float r = 1.0f / fmaxf((float)(end - beg), 1.0f);
        __half2 p0 = __floats2half2_rn(acc[0] * r, acc[1] * r);
        __half2 p1 = __floats2half2_rn(acc[2] * r, acc[3] * r);
        __half2 p2 = __floats2half2_rn(acc[4] * r, acc[5] * r);
        __half2 p3 = __floats2half2_rn(acc[6] * r, acc[7] * r);
        uint4 u;
        u.x = *(unsigned*)&p0; u.y = *(unsigned*)&p1;
        u.z = *(unsigned*)&p2; u.w = *(unsigned*)&p3;
        ((uint4*)g_agg1)[(size_t)n * 16 + l16] = u;
    }
}

// layer-1 GEMM on tensor cores:
//   h = relu( concat(agg1, x) @ Wcat^T + b1 ),  fp16 operands, fp32 accum.
__global__ void __launch_bounds__(256) k_gemm1_mma(const float* __restrict__ b1) {
    __shared__ __half sA[128][72];   // 64 data halves + 8 pad
    __shared__ __half sW[128][72];
    __shared__ float  sb[128];

    int tid = threadIdx.x;
    int lane = tid & 31;
    int w = tid >> 5;
    int n0 = blockIdx.x * 128;

    if (tid < 128) sb[tid] = __ldg(&b1[tid]);

    float acc[16][4];
#pragma unroll
    for (int t = 0; t < 16; t++)
#pragma unroll
        for (int j = 0; j < 4; j++) acc[t][j] = 0.f;

    const uint4* A1 = (const uint4*)g_agg1;
    const uint4* AX = (const uint4*)g_xh;
    const uint4* WC = (const uint4*)g_Wcat;

    for (int c = 0; c < 4; c++) {
        for (int i = tid; i < 1024; i += 256) {
            int r = i >> 3, c8 = i & 7;
            int node = min(n0 + r, N_NODES - 1);
            uint4 va = (c < 2) ? __ldg(&A1[(size_t)node * 16 + c * 8 + c8])
                               : __ldg(&AX[(size_t)node * 16 + (c - 2) * 8 + c8]);
            *(uint4*)&sA[r][c8 * 8] = va;
            uint4 vw = __ldg(&WC[r * 32 + c * 8 + c8]);
            *(uint4*)&sW[r][c8 * 8] = vw;
        }
        __syncthreads();

#pragma unroll
        for (int ks = 0; ks < 4; ks++) {
            uint32_t a[4];
            int ar = w * 16 + (lane >> 2);
            int ah = ks * 16 + (lane & 3) * 2;
            a[0] = *(const uint32_t*)&sA[ar][ah];
            a[1] = *(const uint32_t*)&sA[ar + 8][ah];
            a[2] = *(const uint32_t*)&sA[ar][ah + 8];
            a[3] = *(const uint32_t*)&sA[ar + 8][ah + 8];
#pragma unroll
            for (int t = 0; t < 16; t++) {
                int br = t * 8 + (lane >> 2);
                uint32_t b0 = *(const uint32_t*)&sW[br][ah];
                uint32_t b1r = *(const uint32_t*)&sW[br][ah + 8];
                mma16816(acc[t], a, b0, b1r);
            }
        }
        __syncthreads();
    }

    int row = w * 16 + (lane >> 2);
    int node0 = n0 + row;
    int node1 = node0 + 8;
#pragma unroll
    for (int t = 0; t < 16; t++) {
        int col = t * 8 + (lane & 3) * 2;
        float b0f = sb[col], b1f = sb[col + 1];
        if (node0 < N_NODES) {
            __half2 p = __floats2half2_rn(fmaxf(acc[t][0] + b0f, 0.f),
                                          fmaxf(acc[t][1] + b1f, 0.f));
            *(uint32_t*)&g_h[(size_t)node0 * 128 + col] = *(uint32_t*)&p;
        }
        if (node1 < N_NODES) {
            __half2 p = __floats2half2_rn(fmaxf(acc[t][2] + b0f, 0.f),
                                          fmaxf(acc[t][3] + b1f, 0.f));
            *(uint32_t*)&g_h[(size_t)node1 * 128 + col] = *(uint32_t*)&p;
        }
    }
}

// layer-2 aggregation fused with pooling (warp per node), 2-edge uint4 gather, fp32 accum
__global__ void k_agg2pool(const void* __restrict__ batch) {
    const int is64 = g_is64;
    int lane = threadIdx.x & 31;
    int n = (blockIdx.x * blockDim.x + threadIdx.x) >> 5;
    if (n >= N_NODES) return;
    int beg = g_rowptr[n], end = g_rowptr[n + 1];
    int half = lane >> 4, l16 = lane & 15;
    float acc[8] = {0.f, 0.f, 0.f, 0.f, 0.f, 0.f, 0.f, 0.f};
    const uint4* h4 = (const uint4*)g_h;
    for (int e0 = beg; e0 < end; e0 += 32) {
        int myc = (e0 + lane < end) ? g_col[e0 + lane] : -1;
        int m = min(32, end - e0);
        int npair = (m + 1) >> 1;
        #pragma unroll 4
        for (int j = 0; j < npair; j++) {
            int s0 = __shfl_sync(0xffffffff, myc, 2 * j);
            int s1 = __shfl_sync(0xffffffff, myc, 2 * j + 1);
            int s = half ? s1 : s0;
            if (s >= 0) {
                uint4 v = __ldg(&h4[(size_t)s * 16 + l16]);
                float2 f0 = __half22float2(*(__half2*)&v.x);
                float2 f1 = __half22float2(*(__half2*)&v.y);
                float2 f2 = __half22float2(*(__half2*)&v.z);
                float2 f3 = __half22float2(*(__half2*)&v.w);
                acc[0] += f0.x; acc[1] += f0.y; acc[2] += f1.x; acc[3] += f1.y;
                acc[4] += f2.x; acc[5] += f2.y; acc[6] += f3.x; acc[7] += f3.y;
            }
        }
    }
#pragma unroll
    for (int c = 0; c < 8; c++) acc[c] += __shfl_xor_sync(0xffffffff, acc[c], 16);

    int g;
    if (is64) g = (int)((const long long*)batch)[n];
    else      g = ((const int*)batch)[n];
    g = min(max(g, 0), N_GRAPHS - 1);

    if (half == 0) {
        float r = 1.0f / fmaxf((float)(end - beg), 1.0f);
        float* pL = g_poolL + g * 128 + l16 * 8;
        asm volatile("red.global.add.v4.f32 [%0], {%1,%2,%3,%4};"
                     :: "l"(pL), "f"(acc[0] * r), "f"(acc[1] * r), "f"(acc[2] * r), "f"(acc[3] * r) : "memory");
        asm volatile("red.global.add.v4.f32 [%0], {%1,%2,%3,%4};"
                     :: "l"(pL + 4), "f"(acc[4] * r), "f"(acc[5] * r), "f"(acc[6] * r), "f"(acc[7] * r) : "memory");

        uint4 hv = __ldg(&h4[(size_t)n * 16 + l16]);
        float2 f0 = __half22float2(*(__half2*)&hv.x);
        float2 f1 = __half22float2(*(__half2*)&hv.y);
        float2 f2 = __half22float2(*(__half2*)&hv.z);
        float2 f3 = __half22float2(*(__half2*)&hv.w);
        float* pR = g_poolR + g * 128 + l16 * 8;
        asm volatile("red.global.add.v4.f32 [%0], {%1,%2,%3,%4};"
                     :: "l"(pR), "f"(f0.x), "f"(f0.y), "f"(f1.x), "f"(f1.y) : "memory");
        asm volatile("red.global.add.v4.f32 [%0], {%1,%2,%3,%4};"
                     :: "l"(pR + 4), "f"(f2.x), "f"(f2.y), "f"(f3.x), "f"(f3.y) : "memory");
        if (lane == 0) atomicAdd(&g_cnt[g], 1.0f);
    }
}

// final: out[g][o] = ( poolL[g]@Wl2[o]^T + poolR[g]@Wr2[o]^T ) / max(cnt,1) + b2[o]
__global__ void k_final(const float* __restrict__ Wl2, const float* __restrict__ Wr2,
                        const float* __restrict__ b2, float* __restrict__ out) {
    __shared__ float pl[128];
    __shared__ float pr[128];
    int g = blockIdx.x;
    int t = threadIdx.x;   // 64 threads
    pl[t]      = g_poolL[g * 128 + t];
    pl[t + 64] = g_poolL[g * 128 + t + 64];
    pr[t]      = g_poolR[g * 128 + t];
    pr[t + 64] = g_poolR[g * 128 + t + 64];
    __syncthreads();
    float c = fmaxf(g_cnt[g], 1.0f);
    float acc = 0.f;
    const float4* wl4 = (const float4*)&Wl2[t * 128];
    const float4* wr4 = (const float4*)&Wr2[t * 128];
#pragma unroll 8
    for (int k4 = 0; k4 < 32; k4++) {
        float4 wl = __ldg(&wl4[k4]);
        float4 wr = __ldg(&wr4[k4]);
        int k = 4 * k4;
        acc += pl[k]     * wl.x + pl[k + 1] * wl.y + pl[k + 2] * wl.z + pl[k + 3] * wl.w;
        acc += pr[k]     * wr.x + pr[k + 1] * wr.y + pr[k + 2] * wr.z + pr[k + 3] * wr.w;
    }
    out[g * 64 + t] = acc / c + __ldg(&b2[t]);
}

// ---------------- launch ----------------
extern "C" void kernel_launch(void* const* d_in, const int* in_sizes, int n_in,
                              void* d_out, int out_size) {
    const float* x     = (const float*)d_in[0];
    const void*  ei    = d_in[1];
    const void*  batch = d_in[2];
    const float* Wl1   = (const float*)d_in[3];
    const float* Wr1   = (const float*)d_in[4];
    const float* b1    = (const float*)d_in[5];
    const float* Wl2   = (const float*)d_in[6];
    const float* Wr2   = (const float*)d_in[7];
    const float* b2    = (const float*)d_in[8];
    float* out = (float*)d_out;

    // fork-join: side stream runs setupB (Wcat + x->fp16 + pool zero) while the
    // main stream builds the CSR. Streams/events are created and destroyed each
    // call (no static state); all ops are capture-legal.
    cudaStream_t s2;
    cudaStreamCreateWithFlags(&s2, cudaStreamNonBlocking);
    cudaEvent_t evFork, evJoin;
    cudaEventCreateWithFlags(&evFork, cudaEventDisableTiming);
    cudaEventCreateWithFlags(&evJoin, cudaEventDisableTiming);

    // main: zero hist counters + detect index dtype
    k_pre<<<160, 256>>>((const int*)ei);
    cudaEventRecord(evFork, 0);
    cudaStreamWaitEvent(s2, evFork, 0);

    // side: Wcat + convert x + zero pools (independent of CSR chain)
    k_setupB<<<2048, 256, 0, s2>>>(Wl1, Wr1, (const float4*)x);
    cudaEventRecord(evJoin, s2);

    // main: build CSR grouped by dst
    k_hist<<<2048, 256>>>(ei);
    k_scan1<<<(N_NODES + 1023) / 1024, 1024>>>();
    k_scan3<<<(N_NODES + 255) / 256, 256>>>();
    k_fill<<<2048, 256>>>(ei);

    // join: agg1 needs g_xh (side stream) + CSR (main stream)
    cudaStreamWaitEvent(0, evJoin, 0);

    // layer 1: gather-mean then tensor-core gemm+relu
    k_agg1<<<(N_NODES * 32 + 255) / 256, 256>>>();
    k_gemm1_mma<<<(N_NODES + 127) / 128, 256>>>(b1);

    // layer 2 aggregation fused with pooling
    k_agg2pool<<<(N_NODES * 32 + 255) / 256, 256>>>(batch);

    // tiny final GEMMs [256,128]x[128,64]
    k_final<<<N_GRAPHS, 64>>>(Wl2, Wr2, b2, out);

    cudaEventDestroy(evFork);
    cudaEventDestroy(evJoin);
    cudaStreamDestroy(s2);
}